// round 3
// baseline (speedup 1.0000x reference)
#include <cuda_runtime.h>

// ---------------- problem constants ----------------
#define L2      2049            // L + 1 (BOS prepended)
#define BSZ     8
#define NPOS    (BSZ * L2)      // 16392
#define CCH     32
#define HH      16
#define NQ      576             // 18 rows x 32 cols: j=0..15 (h2), 16 (gsum/k3b), 17 (self/skipW)
#define NGROUPS (NPOS / 4)      // 4098 (exact)
#define NBLK    148
#define NWARPS  16
#define NTHREADS 512

// ---------------- shared memory layout (float offsets) ----------------
#define W3_OFF   0
#define W3_SZ    (18 * 1024)        // rows: 16 x k3W, 1 x k3b, 1 x skipW
#define PK1W     (W3_OFF + W3_SZ)   // 16
#define PK1B     (PK1W + 16)        // 16
#define PK2W     (PK1B + 16)        // 256
#define PK2B     (PK2W + 256)       // 16
#define PSKB     (PK2B + 16)        // 32
#define U_OFF    (PSKB + 32)        // 18768 (16B aligned)
#define U_STRIDE (NQ * 4)           // 2304 floats per warp
#define ST_OFF   (U_OFF + NWARPS * U_STRIDE)  // 55632
#define SMEM_FLOATS (ST_OFF + 64)   // 55696
#define SMEM_BYTES  (SMEM_FLOATS * 4) // 222784 B (< 227KB opt-in)

// ---------------- device scratch ----------------
__device__ float g_times[NPOS];
__device__ float g_bufA[NPOS * CCH];
__device__ float g_bufB[NPOS * CCH];
__device__ float g_part[NBLK * 64];   // per-block [sum[32], sumsq[32]]
__device__ float g_bn[64];            // scale[32], shift[32]
__device__ int   g_bos;

__device__ __forceinline__ float lrelu(float x) { return fmaxf(x, 0.1f * x); }

// ---------------- prep: times buffer ----------------
__global__ void k_prep(const float* __restrict__ et) {
    int i = blockIdx.x * blockDim.x + threadIdx.x;
    if (i < NPOS) {
        int b = i / L2, l = i - b * L2;
        g_times[i] = (l == 0) ? 0.0f : et[b * 2048 + l - 1];
    }
}

// ---------------- max(event_types)+1 ----------------
__global__ void k_maxtype(const int* __restrict__ ty) {
    __shared__ int s[256];
    int m = 0;
    for (int i = threadIdx.x; i < BSZ * 2048; i += 256) m = max(m, ty[i]);
    s[threadIdx.x] = m;
    __syncthreads();
    for (int o = 128; o > 0; o >>= 1) {
        if (threadIdx.x < o) s[threadIdx.x] = max(s[threadIdx.x], s[threadIdx.x + o]);
        __syncthreads();
    }
    if (threadIdx.x == 0) g_bos = s[0] + 1;
}

// ---------------- embedding gather ----------------
__global__ void k_embed(const int* __restrict__ ty, const float* __restrict__ emb) {
    int i = blockIdx.x * blockDim.x + threadIdx.x;
    if (i < NPOS * CCH) {
        int c = i & 31;
        int p = i >> 5;
        int b = p / L2, l = p - b * L2;
        int t = (l == 0) ? g_bos : ty[b * 2048 + l - 1];
        g_bufA[i] = (t == 0) ? 0.0f : emb[t * CCH + c];  // emb row 0 forced to 0
    }
}

// ---------------- main fused layer kernel ----------------
extern __shared__ float smem[];

__global__ void __launch_bounds__(NTHREADS, 1) k_layer(
    int sel,               // 0: in=A out=B ; 1: in=B out=A
    int dil,
    const float* __restrict__ k1W, const float* __restrict__ k1b,
    const float* __restrict__ k2W, const float* __restrict__ k2b,
    const float* __restrict__ k3W, const float* __restrict__ k3b,
    const float* __restrict__ skW, const float* __restrict__ skb)
{
    const float* __restrict__ encIn = sel ? g_bufB : g_bufA;
    float* __restrict__ outBuf      = sel ? g_bufA : g_bufB;

    // Stage W3 (k3W rows 0..15, k3b row 16, skipW row 17) into shared
    for (int i = threadIdx.x; i < W3_SZ; i += NTHREADS) {
        float v;
        if (i < 16384)       v = k3W[i];
        else if (i < 17408)  v = k3b[i - 16384];
        else                 v = skW[i - 17408];
        smem[W3_OFF + i] = v;
    }
    for (int i = threadIdx.x; i < 336; i += NTHREADS) {
        float v;
        if (i < 16)        v = k1W[i];
        else if (i < 32)   v = k1b[i - 16];
        else if (i < 288)  v = k2W[i - 32];
        else if (i < 304)  v = k2b[i - 288];
        else               v = skb[i - 304];
        smem[PK1W + i] = v;
    }
    if (threadIdx.x < 64) smem[ST_OFF + threadIdx.x] = 0.0f;
    __syncthreads();

    const int warp = threadIdx.x >> 5;
    const int lane = threadIdx.x & 31;
    float* Uw = smem + U_OFF + warp * U_STRIDE;
    const float* k1w_s = smem + PK1W;
    const float* k1b_s = smem + PK1B;
    const float* k2w_s = smem + PK2W;
    const float* k2b_s = smem + PK2B;

    for (int grp = blockIdx.x * NWARPS + warp; grp < NGROUPS; grp += NBLK * NWARPS) {
        // ---- Phase A: form U for 4 positions (2 pairs of float2) ----
        #pragma unroll
        for (int pair = 0; pair < 2; pair++) {
            float2 u[16];
            float2 gs    = make_float2(0.f, 0.f);
            float2 fself = make_float2(0.f, 0.f);
            #pragma unroll
            for (int j = 0; j < 16; j++) u[j] = make_float2(0.f, 0.f);

            #pragma unroll
            for (int half = 0; half < 2; half++) {
                int p = grp * 4 + pair * 2 + half;
                int b = p / L2, l = p - b * L2;
                float t_l = g_times[p];
                float fs = encIn[p * CCH + lane];          // self features (skip path)
                if (half == 0) fself.x = fs; else fself.y = fs;

                if (t_l != 0.0f) {                          // mask at current position
                    for (int k = 0; k < 5; k++) {
                        int ii = l - k * dil;
                        int ic = ii < 0 ? 0 : ii;
                        float t_i = g_times[b * L2 + ic];
                        if (ii < 0 || t_i == 0.0f) continue; // warp-uniform mask
                        float dt = t_l - t_i;

                        // kernel MLP: 1 -> 16 -> 16
                        float h1[16];
                        #pragma unroll
                        for (int jj = 0; jj < 16; jj++)
                            h1[jj] = lrelu(fmaf(dt, k1w_s[jj], k1b_s[jj]));
                        int jm = lane & 15;
                        float a = k2b_s[jm];
                        #pragma unroll
                        for (int jj = 0; jj < 16; jj++)
                            a = fmaf(h1[jj], k2w_s[jj * 16 + jm], a);
                        float h2 = lrelu(a);

                        // gather features & rank-1 update
                        float f = encIn[(b * L2 + ic) * CCH + lane];
                        #pragma unroll
                        for (int j = 0; j < 16; j++) {
                            float hj = __shfl_sync(0xffffffffu, h2, j);
                            if (half == 0) u[j].x = fmaf(hj, f, u[j].x);
                            else           u[j].y = fmaf(hj, f, u[j].y);
                        }
                        if (half == 0) gs.x += f; else gs.y += f;
                    }
                }
            }
            #pragma unroll
            for (int j = 0; j < 16; j++)
                *(float2*)&Uw[(j * 32 + lane) * 4 + pair * 2] = u[j];
            *(float2*)&Uw[(16 * 32 + lane) * 4 + pair * 2] = gs;
            *(float2*)&Uw[(17 * 32 + lane) * 4 + pair * 2] = fself;
        }
        __syncwarp();

        // ---- Phase B: contraction out[p,d] = sum_q U[q,p] * W3[q,d] ----
        float4 acc = make_float4(0.f, 0.f, 0.f, 0.f);
        #pragma unroll 8
        for (int q = 0; q < NQ; q++) {
            float w = smem[W3_OFF + q * 32 + lane];          // conflict-free
            float4 u4 = *(const float4*)&Uw[q * 4];          // broadcast
            acc.x = fmaf(u4.x, w, acc.x);
            acc.y = fmaf(u4.y, w, acc.y);
            acc.z = fmaf(u4.z, w, acc.z);
            acc.w = fmaf(u4.w, w, acc.w);
        }
        float sb = smem[PSKB + lane];
        acc.x += sb; acc.y += sb; acc.z += sb; acc.w += sb;

        int p0 = grp * 4;
        outBuf[(p0 + 0) * CCH + lane] = acc.x;
        outBuf[(p0 + 1) * CCH + lane] = acc.y;
        outBuf[(p0 + 2) * CCH + lane] = acc.z;
        outBuf[(p0 + 3) * CCH + lane] = acc.w;

        // per-block BN partials
        atomicAdd(&smem[ST_OFF + lane], acc.x + acc.y + acc.z + acc.w);
        atomicAdd(&smem[ST_OFF + 32 + lane],
                  acc.x * acc.x + acc.y * acc.y + acc.z * acc.z + acc.w * acc.w);
        __syncwarp();   // protect Uw before next group's stores
    }

    __syncthreads();
    if (threadIdx.x < 64)
        g_part[blockIdx.x * 64 + threadIdx.x] = smem[ST_OFF + threadIdx.x];
}

// ---------------- BN stats finalize ----------------
__global__ void k_bnstats(const float* __restrict__ gamma, const float* __restrict__ beta) {
    int c = threadIdx.x;
    if (c < 32) {
        float s = 0.f, sq = 0.f;
        for (int b = 0; b < NBLK; b++) {
            s  += g_part[b * 64 + c];
            sq += g_part[b * 64 + 32 + c];
        }
        const float inv = 1.0f / (float)NPOS;
        float mu  = s * inv;
        float var = sq * inv - mu * mu;
        float rs  = rsqrtf(var + 1e-5f);
        float sc  = rs * gamma[c];
        g_bn[c]      = sc;
        g_bn[32 + c] = beta[c] - mu * sc;
    }
}

// ---------------- BN apply + leaky relu ----------------
__global__ void k_bnapply(int sel, float* dst_ext) {
    float* src = sel ? g_bufA : g_bufB;   // same sel as the producing k_layer
    float* dst = dst_ext ? dst_ext : src;
    int i = blockIdx.x * blockDim.x + threadIdx.x;
    if (i < NPOS * CCH) {
        int c = i & 31;
        float y = fmaf(src[i], g_bn[c], g_bn[32 + c]);
        dst[i] = fmaxf(y, 0.1f * y);
    }
}

// ---------------- launch ----------------
extern "C" void kernel_launch(void* const* d_in, const int* in_sizes, int n_in,
                              void* d_out, int out_size) {
    const float* et    = (const float*)d_in[0];
    const int*   ty    = (const int*)  d_in[1];
    const float* emb   = (const float*)d_in[2];
    const float* k1W   = (const float*)d_in[3];
    const float* k1b   = (const float*)d_in[4];
    const float* k2W   = (const float*)d_in[5];
    const float* k2b   = (const float*)d_in[6];
    const float* k3W   = (const float*)d_in[7];
    const float* k3b   = (const float*)d_in[8];
    const float* skW   = (const float*)d_in[9];
    const float* skb   = (const float*)d_in[10];
    const float* gamma = (const float*)d_in[11];
    const float* beta  = (const float*)d_in[12];

    cudaFuncSetAttribute(k_layer, cudaFuncAttributeMaxDynamicSharedMemorySize, SMEM_BYTES);

    k_prep<<<(NPOS + 255) / 256, 256>>>(et);
    k_maxtype<<<1, 256>>>(ty);
    k_embed<<<(NPOS * CCH + 255) / 256, 256>>>(ty, emb);

    const int dils[4] = {1, 2, 4, 8};
    for (int L = 0; L < 4; L++) {
        int sel = L & 1;
        k_layer<<<NBLK, NTHREADS, SMEM_BYTES>>>(
            sel, dils[L],
            k1W + L * 16,   k1b + L * 16,
            k2W + L * 256,  k2b + L * 16,
            k3W + L * 16384, k3b + L * 1024,
            skW + L * 1024, skb + L * 32);
        k_bnstats<<<1, 32>>>(gamma + L * 32, beta + L * 32);
        k_bnapply<<<(NPOS * CCH + 255) / 256, 256>>>(
            sel, (L == 3) ? (float*)d_out : nullptr);
    }
}

// round 4
// speedup vs baseline: 1.0548x; 1.0548x over previous
#include <cuda_runtime.h>
#include <cstdint>

// ---------------- problem constants ----------------
#define L2      2049            // L + 1 (BOS prepended)
#define BSZ     8
#define NPOS    (BSZ * L2)      // 16392
#define NG      513             // ceil(NPOS/32)
#define NPAD    (NG * 32)       // 16416
#define CCH     32
#define NQ      576             // 18 rows x 32 cols
#define NBLK    148
#define NWARPS  16
#define NTHREADS 512
#define QPW     36              // q rows per warp (16*36 = 576)

// ---------------- shared memory layout (float word offsets) ----------------
#define W3_OFF   0
#define W3_SZ    (18 * 1024)        // 18432: 16 x k3W rows, k3b, skipW
#define PK1W     (W3_OFF + W3_SZ)   // 18432
#define PK1B     (PK1W + 16)
#define PK2W     (PK1B + 16)
#define PK2B     (PK2W + 256)
#define PSKB     (PK2B + 16)        // 18736 .. 18768
#define U_OFF    18784              // 16B aligned
#define U_ROW    34                 // padded row (bank/conflict + alignment)
#define U_SZ     (NQ * U_ROW)       // 19584
#define PART_OFF U_OFF              // partial tiles reuse U region
#define PART_WS  1152               // 32 * 36 words per warp tile
#define ST_OFF   (U_OFF + U_SZ)     // 38368
#define SMEM_WORDS (ST_OFF + 64)    // 38432
#define SMEM_BYTES (SMEM_WORDS * 4) // 153728 B

// ---------------- device scratch ----------------
__device__ float g_times[NPAD];
__device__ float g_bufA[NPAD * CCH];
__device__ float g_bufB[NPAD * CCH];   // zero-init; pad region never written
__device__ float g_part[NBLK * 64];
__device__ float g_bn[64];
__device__ int   g_bos;

__device__ __forceinline__ float lrelu(float x) { return fmaxf(x, 0.1f * x); }

// ---------------- prep: times buffer (padded) ----------------
__global__ void k_prep(const float* __restrict__ et) {
    int i = blockIdx.x * blockDim.x + threadIdx.x;
    if (i < NPAD) {
        if (i >= NPOS) { g_times[i] = 0.0f; return; }
        int b = i / L2, l = i - b * L2;
        g_times[i] = (l == 0) ? 0.0f : et[b * 2048 + l - 1];
    }
}

// ---------------- max(event_types)+1 ----------------
__global__ void k_maxtype(const int* __restrict__ ty) {
    __shared__ int s[256];
    int m = 0;
    for (int i = threadIdx.x; i < BSZ * 2048; i += 256) m = max(m, ty[i]);
    s[threadIdx.x] = m;
    __syncthreads();
    for (int o = 128; o > 0; o >>= 1) {
        if (threadIdx.x < o) s[threadIdx.x] = max(s[threadIdx.x], s[threadIdx.x + o]);
        __syncthreads();
    }
    if (threadIdx.x == 0) g_bos = s[0] + 1;
}

// ---------------- embedding gather (padded, pad -> 0) ----------------
__global__ void k_embed(const int* __restrict__ ty, const float* __restrict__ emb) {
    int i = blockIdx.x * blockDim.x + threadIdx.x;
    if (i < NPAD * CCH) {
        int c = i & 31;
        int p = i >> 5;
        float v = 0.0f;
        if (p < NPOS) {
            int b = p / L2, l = p - b * L2;
            int t = (l == 0) ? g_bos : ty[b * 2048 + l - 1];
            v = (t == 0) ? 0.0f : emb[t * CCH + c];
        }
        g_bufA[i] = v;
    }
}

// ---------------- main fused layer kernel ----------------
extern __shared__ float smem[];

__global__ void __launch_bounds__(NTHREADS, 1) k_layer(
    int sel, int dil,
    const float* __restrict__ k1W, const float* __restrict__ k1b,
    const float* __restrict__ k2W, const float* __restrict__ k2b,
    const float* __restrict__ k3W, const float* __restrict__ k3b,
    const float* __restrict__ skW, const float* __restrict__ skb)
{
    const float* __restrict__ encIn = sel ? g_bufB : g_bufA;
    float* __restrict__ outBuf      = sel ? g_bufA : g_bufB;

    // Stage W3 (k3W rows, k3b row-block, skipW row-block) + small params
    for (int i = threadIdx.x; i < W3_SZ; i += NTHREADS) {
        float v;
        if (i < 16384)       v = k3W[i];
        else if (i < 17408)  v = k3b[i - 16384];
        else                 v = skW[i - 17408];
        smem[W3_OFF + i] = v;
    }
    for (int i = threadIdx.x; i < 336; i += NTHREADS) {
        float v;
        if (i < 16)        v = k1W[i];
        else if (i < 32)   v = k1b[i - 16];
        else if (i < 288)  v = k2W[i - 32];
        else if (i < 304)  v = k2b[i - 288];
        else               v = skb[i - 304];
        smem[PK1W + i] = v;
    }
    if (threadIdx.x < 64) smem[ST_OFF + threadIdx.x] = 0.0f;
    __syncthreads();

    const int tid  = threadIdx.x;
    const int warp = tid >> 5;
    const int lane = tid & 31;
    const float* k1w_s = smem + PK1W;
    const float* k1b_s = smem + PK1B;
    const float* k2w_s = smem + PK2W;
    const float* k2b_s = smem + PK2B;

    // reduce-stage mapping: element e0 = 2*tid -> (p = tid>>4, d0 = (2*tid)&31)
    const int rp = tid >> 4;
    const int rd = (2 * tid) & 31;
    float st_s0 = 0.f, st_s1 = 0.f, st_q0 = 0.f, st_q1 = 0.f;

    for (int grp = blockIdx.x; grp < NG; grp += NBLK) {
        // ================= Phase A: this warp fills U columns 2w, 2w+1 =====
        {
            float2 u[16];
            float2 gs    = make_float2(0.f, 0.f);
            float2 fself = make_float2(0.f, 0.f);
            #pragma unroll
            for (int j = 0; j < 16; j++) u[j] = make_float2(0.f, 0.f);

            #pragma unroll
            for (int half = 0; half < 2; half++) {
                int p = grp * 32 + warp * 2 + half;
                float t_l = g_times[p];
                float fs = encIn[p * CCH + lane];
                if (half == 0) fself.x = fs; else fself.y = fs;

                if (t_l != 0.0f) {
                    int b = p / L2, l = p - b * L2;
                    // batch the 5 gather loads up front (hide L2 latency)
                    float fvk[5], dtk[5];
                    int valm = 0;
                    #pragma unroll
                    for (int k = 0; k < 5; k++) {
                        int ii = l - k * dil;
                        int ic = ii < 0 ? 0 : ii;
                        float ti = g_times[b * L2 + ic];
                        dtk[k] = t_l - ti;
                        fvk[k] = encIn[(b * L2 + ic) * CCH + lane];
                        if (ii >= 0 && ti != 0.0f) valm |= (1 << k);
                    }
                    #pragma unroll
                    for (int k = 0; k < 5; k++) {
                        if (valm & (1 << k)) {       // warp-uniform
                            float dt = dtk[k];
                            float h1[16];
                            #pragma unroll
                            for (int jj = 0; jj < 16; jj++)
                                h1[jj] = lrelu(fmaf(dt, k1w_s[jj], k1b_s[jj]));
                            int jm = lane & 15;
                            float a = k2b_s[jm];
                            #pragma unroll
                            for (int jj = 0; jj < 16; jj++)
                                a = fmaf(h1[jj], k2w_s[jj * 16 + jm], a);
                            float h2 = lrelu(a);

                            float f = fvk[k];
                            #pragma unroll
                            for (int j = 0; j < 16; j++) {
                                float hj = __shfl_sync(0xffffffffu, h2, j);
                                if (half == 0) u[j].x = fmaf(hj, f, u[j].x);
                                else           u[j].y = fmaf(hj, f, u[j].y);
                            }
                            if (half == 0) gs.x += f; else gs.y += f;
                        }
                    }
                }
            }
            // store U columns (row = q, padded row stride 34, cols 2w,2w+1)
            #pragma unroll
            for (int j = 0; j < 16; j++)
                *(float2*)&smem[U_OFF + (j * 32 + lane) * U_ROW + warp * 2] = u[j];
            *(float2*)&smem[U_OFF + (512 + lane) * U_ROW + warp * 2] = gs;
            *(float2*)&smem[U_OFF + (544 + lane) * U_ROW + warp * 2] = fself;
        }
        __syncthreads();

        // ================= Phase B: warp contracts q in [w*36, w*36+36) =====
        // lane = position; acc[k] = packed f32x2 over output channels (2k, 2k+1)
        unsigned long long acc[16];
        #pragma unroll
        for (int i = 0; i < 16; i++) acc[i] = 0ull;
        {
            const int q0 = warp * QPW;
            const float* Uq  = smem + U_OFF + q0 * U_ROW + lane;
            const float* W3q = smem + W3_OFF + q0 * 32;
            #pragma unroll 2
            for (int qq = 0; qq < QPW; qq++) {
                float uv = Uq[qq * U_ROW];
                unsigned long long uu;
                asm("mov.b64 %0, {%1, %1};" : "=l"(uu) : "r"(__float_as_uint(uv)));
                const ulonglong2* wrow = (const ulonglong2*)(W3q + qq * 32);
                #pragma unroll
                for (int d4 = 0; d4 < 8; d4++) {
                    ulonglong2 w2 = wrow[d4];
                    asm("fma.rn.f32x2 %0, %1, %2, %0;" : "+l"(acc[2*d4])   : "l"(w2.x), "l"(uu));
                    asm("fma.rn.f32x2 %0, %1, %2, %0;" : "+l"(acc[2*d4+1]) : "l"(w2.y), "l"(uu));
                }
            }
        }
        __syncthreads();   // everyone done reading U (region reused below)

        // writeback partial tile: part[warp][p=lane][d], row stride 36
        {
            ulonglong2* pb = (ulonglong2*)&smem[PART_OFF + warp * PART_WS + lane * 36];
            #pragma unroll
            for (int i = 0; i < 8; i++)
                pb[i] = make_ulonglong2(acc[2*i], acc[2*i+1]);
        }
        __syncthreads();

        // tree-reduce 16 partials; add skipb; store; accumulate BN stats
        {
            float s0 = 0.f, s1 = 0.f;
            const float* rb = smem + PART_OFF + rp * 36 + rd;
            #pragma unroll
            for (int w = 0; w < 16; w++) {
                float2 v = *(const float2*)(rb + w * PART_WS);
                s0 += v.x; s1 += v.y;
            }
            s0 += smem[PSKB + rd];
            s1 += smem[PSKB + rd + 1];
            int pg = grp * 32 + rp;
            if (pg < NPOS) {
                *(float2*)&outBuf[pg * CCH + rd] = make_float2(s0, s1);
                st_s0 += s0; st_s1 += s1;
                st_q0 += s0 * s0; st_q1 += s1 * s1;
            }
        }
        __syncthreads();   // before next group's Phase A overwrites U region
    }

    // flush BN stat partials
    atomicAdd(&smem[ST_OFF + rd],      st_s0);
    atomicAdd(&smem[ST_OFF + rd + 1],  st_s1);
    atomicAdd(&smem[ST_OFF + 32 + rd],     st_q0);
    atomicAdd(&smem[ST_OFF + 32 + rd + 1], st_q1);
    __syncthreads();
    if (tid < 64)
        g_part[blockIdx.x * 64 + tid] = smem[ST_OFF + tid];
}

// ---------------- BN stats finalize ----------------
__global__ void k_bnstats(const float* __restrict__ gamma, const float* __restrict__ beta) {
    int c = threadIdx.x;
    if (c < 32) {
        float s = 0.f, sq = 0.f;
        for (int b = 0; b < NBLK; b++) {
            s  += g_part[b * 64 + c];
            sq += g_part[b * 64 + 32 + c];
        }
        const float inv = 1.0f / (float)NPOS;
        float mu  = s * inv;
        float var = sq * inv - mu * mu;
        float rs  = rsqrtf(var + 1e-5f);
        float sc  = rs * gamma[c];
        g_bn[c]      = sc;
        g_bn[32 + c] = beta[c] - mu * sc;
    }
}

// ---------------- BN apply + leaky relu ----------------
__global__ void k_bnapply(int sel, float* dst_ext) {
    float* src = sel ? g_bufA : g_bufB;   // same sel as the producing k_layer
    float* dst = dst_ext ? dst_ext : src;
    int i = blockIdx.x * blockDim.x + threadIdx.x;
    if (i < NPOS * CCH) {
        int c = i & 31;
        float y = fmaf(src[i], g_bn[c], g_bn[32 + c]);
        dst[i] = fmaxf(y, 0.1f * y);
    }
}

// ---------------- launch ----------------
extern "C" void kernel_launch(void* const* d_in, const int* in_sizes, int n_in,
                              void* d_out, int out_size) {
    const float* et    = (const float*)d_in[0];
    const int*   ty    = (const int*)  d_in[1];
    const float* emb   = (const float*)d_in[2];
    const float* k1W   = (const float*)d_in[3];
    const float* k1b   = (const float*)d_in[4];
    const float* k2W   = (const float*)d_in[5];
    const float* k2b   = (const float*)d_in[6];
    const float* k3W   = (const float*)d_in[7];
    const float* k3b   = (const float*)d_in[8];
    const float* skW   = (const float*)d_in[9];
    const float* skb   = (const float*)d_in[10];
    const float* gamma = (const float*)d_in[11];
    const float* beta  = (const float*)d_in[12];

    cudaFuncSetAttribute(k_layer, cudaFuncAttributeMaxDynamicSharedMemorySize, SMEM_BYTES);

    k_prep<<<(NPAD + 255) / 256, 256>>>(et);
    k_maxtype<<<1, 256>>>(ty);
    k_embed<<<(NPAD * CCH + 255) / 256, 256>>>(ty, emb);

    const int dils[4] = {1, 2, 4, 8};
    for (int L = 0; L < 4; L++) {
        int sel = L & 1;
        k_layer<<<NBLK, NTHREADS, SMEM_BYTES>>>(
            sel, dils[L],
            k1W + L * 16,   k1b + L * 16,
            k2W + L * 256,  k2b + L * 16,
            k3W + L * 16384, k3b + L * 1024,
            skW + L * 1024, skb + L * 32);
        k_bnstats<<<1, 32>>>(gamma + L * 32, beta + L * 32);
        k_bnapply<<<(NPOS * CCH + 255) / 256, 256>>>(
            sel, (L == 3) ? (float*)d_out : nullptr);
    }
}

// round 7
// speedup vs baseline: 1.2812x; 1.2145x over previous
#include <cuda_runtime.h>
#include <cstdint>

// ---------------- problem constants ----------------
#define L2      2049            // L + 1 (BOS prepended)
#define BSZ     8
#define NPOS    (BSZ * L2)      // 16392
#define NPAD2   16512           // 129 * 128 (padded position count)
#define CCH     32
#define NQ      576             // 16*32 (k3W) + 32 (k3b) + 32 (skipW)
// formU
#define FU_THREADS 128
#define FU_P    32              // positions per formU block
#define NFU     (NPAD2 / FU_P)  // 516
// gemm
#define KSPLIT  6
#define KPB     (NQ / KSPLIT)   // 96
#define KC      32              // k chunk
#define MT      128             // M tile
#define NMT     (NPAD2 / MT)    // 129
#define US_LD   33              // padded U-tile row stride
// reduce
#define RED_BLKS (NPAD2 / 64)   // 258

// ---------------- device scratch ----------------
__device__ float g_times[NPAD2];
__device__ float g_bufA[NPAD2 * CCH];
__device__ float g_bufB[NPAD2 * CCH];        // zero-init; pad rows stay 0
__device__ float g_U[NPAD2 * NQ];            // 38 MB (L2-resident)
__device__ float g_Cp[KSPLIT * NPAD2 * CCH]; // 12.7 MB GEMM partials
__device__ float g_part[RED_BLKS * 64];
__device__ float g_bn[64];
__device__ int   g_bos;

__device__ __forceinline__ float lrelu(float x) { return fmaxf(x, 0.1f * x); }

__device__ __forceinline__ unsigned long long pk2(float x, float y) {
    unsigned long long r;
    asm("mov.b64 %0, {%1,%2};" : "=l"(r) : "r"(__float_as_uint(x)), "r"(__float_as_uint(y)));
    return r;
}
__device__ __forceinline__ unsigned long long dup2(float x) {
    unsigned long long r;
    asm("mov.b64 %0, {%1,%1};" : "=l"(r) : "r"(__float_as_uint(x)));
    return r;
}
__device__ __forceinline__ void fma2(unsigned long long& a, unsigned long long b, unsigned long long c) {
    asm("fma.rn.f32x2 %0, %1, %2, %0;" : "+l"(a) : "l"(b), "l"(c));
}
__device__ __forceinline__ float f2lo(unsigned long long v) { return __uint_as_float((unsigned)(v & 0xffffffffull)); }
__device__ __forceinline__ float f2hi(unsigned long long v) { return __uint_as_float((unsigned)(v >> 32)); }

// ---------------- prep: times buffer (padded) ----------------
__global__ void k_prep(const float* __restrict__ et) {
    int i = blockIdx.x * blockDim.x + threadIdx.x;
    if (i < NPAD2) {
        float v = 0.0f;
        if (i < NPOS) {
            int b = i / L2, l = i - b * L2;
            v = (l == 0) ? 0.0f : et[b * 2048 + l - 1];
        }
        g_times[i] = v;
    }
}

// ---------------- max(event_types)+1 ----------------
__global__ void k_maxtype(const int* __restrict__ ty) {
    __shared__ int s[256];
    int m = 0;
    for (int i = threadIdx.x; i < BSZ * 2048; i += 256) m = max(m, ty[i]);
    s[threadIdx.x] = m;
    __syncthreads();
    for (int o = 128; o > 0; o >>= 1) {
        if (threadIdx.x < o) s[threadIdx.x] = max(s[threadIdx.x], s[threadIdx.x + o]);
        __syncthreads();
    }
    if (threadIdx.x == 0) g_bos = s[0] + 1;
}

// ---------------- embedding gather (padded, pad -> 0) ----------------
__global__ void k_embed(const int* __restrict__ ty, const float* __restrict__ emb) {
    int i = blockIdx.x * blockDim.x + threadIdx.x;
    if (i < NPAD2 * CCH) {
        int c = i & 31;
        int p = i >> 5;
        float v = 0.0f;
        if (p < NPOS) {
            int b = p / L2, l = p - b * L2;
            int t = (l == 0) ? g_bos : ty[b * 2048 + l - 1];
            v = (t == 0) ? 0.0f : emb[t * CCH + c];
        }
        g_bufA[i] = v;
    }
}

// ---------------- k_formU: MLP batch + rank-5 U assembly ----------------
__global__ void __launch_bounds__(FU_THREADS) k_formU(
    int sel, int dil,
    const float* __restrict__ k1W, const float* __restrict__ k1b,
    const float* __restrict__ k2W, const float* __restrict__ k2b)
{
    const float* __restrict__ encIn = sel ? g_bufB : g_bufA;

    __shared__ float sh_par[304];          // k1W[16] k1b[16] k2W[256] k2b[16]
    __shared__ float sh_h[FU_P * 84];      // h2*m per (pos, tap*16+j); stride 84 keeps 16B align
    __shared__ float sh_m[5 * 36];         // mask [tap][pos]

    const int tid = threadIdx.x;

    for (int i = tid; i < 304; i += FU_THREADS) {
        float v;
        if (i < 16)        v = k1W[i];
        else if (i < 32)   v = k1b[i - 16];
        else if (i < 288)  v = k2W[i - 32];
        else               v = k2b[i - 288];
        sh_par[i] = v;
    }
    __syncthreads();

    // ---- stage 1: 160 MLP instances (pos,tap), one per thread ----
    for (int inst = tid; inst < 5 * FU_P; inst += FU_THREADS) {
        int tap = inst >> 5, pos = inst & 31;
        int pg = blockIdx.x * FU_P + pos;
        int pgc = pg < NPOS ? pg : NPOS - 1;   // clamp for safe addressing
        int b = pgc / L2, l = pgc - b * L2;
        float t_l = (pg < NPOS) ? g_times[pg] : 0.0f;
        int ii = l - tap * dil;
        int ic = ii < 0 ? 0 : ii;
        float t_i = g_times[b * L2 + ic];
        float m = (ii >= 0 && t_i != 0.0f && t_l != 0.0f) ? 1.0f : 0.0f;
        float dt = t_l - t_i;

        float h1[16];
        #pragma unroll
        for (int j = 0; j < 16; j++)
            h1[j] = lrelu(fmaf(dt, sh_par[j], sh_par[16 + j]));

        float a[16];
        #pragma unroll
        for (int j = 0; j < 16; j++) a[j] = sh_par[288 + j];
        #pragma unroll
        for (int jj = 0; jj < 16; jj++) {
            float hv = h1[jj];
            const float4* w4 = (const float4*)&sh_par[32 + jj * 16];
            #pragma unroll
            for (int q = 0; q < 4; q++) {
                float4 w = w4[q];
                a[q * 4 + 0] = fmaf(hv, w.x, a[q * 4 + 0]);
                a[q * 4 + 1] = fmaf(hv, w.y, a[q * 4 + 1]);
                a[q * 4 + 2] = fmaf(hv, w.z, a[q * 4 + 2]);
                a[q * 4 + 3] = fmaf(hv, w.w, a[q * 4 + 3]);
            }
        }
        float* hrow = &sh_h[pos * 84 + tap * 16];
        #pragma unroll
        for (int j = 0; j < 16; j++) hrow[j] = lrelu(a[j]) * m;
        sh_m[tap * 36 + pos] = m;
    }
    __syncthreads();

    // ---- stage 2: U assembly, warp = 8 positions, lane = channel ----
    const int warp = tid >> 5, lane = tid & 31;
    for (int pp = 0; pp < 8; pp++) {
        int pos = warp * 8 + pp;
        int pg = blockIdx.x * FU_P + pos;
        int pgc = pg < NPOS ? pg : NPOS - 1;
        int b = pgc / L2, l = pgc - b * L2;

        float f[5];
        #pragma unroll
        for (int tap = 0; tap < 5; tap++) {
            int ii = l - tap * dil;
            int ic = ii < 0 ? 0 : ii;
            f[tap] = encIn[(b * L2 + ic) * CCH + lane];
        }

        float u[16];
        #pragma unroll
        for (int j = 0; j < 16; j++) u[j] = 0.0f;
        float gs = 0.0f;

        #pragma unroll
        for (int tap = 0; tap < 5; tap++) {
            float ft = f[tap];
            gs = fmaf(sh_m[tap * 36 + pos], ft, gs);
            const float4* h4 = (const float4*)&sh_h[pos * 84 + tap * 16];
            #pragma unroll
            for (int q = 0; q < 4; q++) {
                float4 h = h4[q];
                u[q * 4 + 0] = fmaf(h.x, ft, u[q * 4 + 0]);
                u[q * 4 + 1] = fmaf(h.y, ft, u[q * 4 + 1]);
                u[q * 4 + 2] = fmaf(h.z, ft, u[q * 4 + 2]);
                u[q * 4 + 3] = fmaf(h.w, ft, u[q * 4 + 3]);
            }
        }
        float fself = (pg < NPOS) ? f[0] : 0.0f;   // tap0 == self

        float* Urow = &g_U[pg * NQ];
        #pragma unroll
        for (int j = 0; j < 16; j++) Urow[j * 32 + lane] = u[j];
        Urow[512 + lane] = gs;
        Urow[544 + lane] = fself;
    }
}

// ---------------- k_gemm: C_partial[ks] = U[:,ksplit] @ W3[ksplit,:] ----------------
__global__ void __launch_bounds__(256, 3) k_gemm(
    const float* __restrict__ k3W, const float* __restrict__ k3b,
    const float* __restrict__ skW)
{
    __shared__ float Us[2][MT * US_LD];    // [pos][k], stride 33
    __shared__ float Ws[2][KC * 32];       // [k][d]

    const int tid = threadIdx.x;
    const int bm = blockIdx.x, ks = blockIdx.y;
    const int k0base = ks * KPB;
    const int tp = tid >> 3;               // 0..31 -> pos group (4 each)
    const int td = tid & 7;                // 0..7  -> d group (4 each)
    const int lr = tid >> 3;               // load row within pass
    const int lc = (tid & 7) * 4;          // load col (floats)

    unsigned long long acc[8];
    #pragma unroll
    for (int i = 0; i < 8; i++) acc[i] = 0ull;

    // initial stage of chunk 0
    {
        int kg = k0base;
        #pragma unroll
        for (int pass = 0; pass < 4; pass++) {
            int r = lr + pass * 32;
            float4 v = *(const float4*)&g_U[(bm * MT + r) * NQ + kg + lc];
            float* d = &Us[0][r * US_LD + lc];
            d[0] = v.x; d[1] = v.y; d[2] = v.z; d[3] = v.w;
        }
        int q = kg + lr;
        float4 w;
        if (q < 512)      w = *(const float4*)&k3W[q * 32 + lc];
        else if (q < 544) w = *(const float4*)&k3b[(q - 512) * 32 + lc];
        else              w = *(const float4*)&skW[(q - 544) * 32 + lc];
        *(float4*)&Ws[0][lr * 32 + lc] = w;
    }
    __syncthreads();

    #pragma unroll
    for (int c = 0; c < KPB / KC; c++) {
        const int buf = c & 1;
        // prefetch next chunk into registers
        float4 preU[4]; float4 preW;
        if (c < KPB / KC - 1) {
            int kg = k0base + (c + 1) * KC;
            #pragma unroll
            for (int pass = 0; pass < 4; pass++)
                preU[pass] = *(const float4*)&g_U[(bm * MT + lr + pass * 32) * NQ + kg + lc];
            int q = kg + lr;
            if (q < 512)      preW = *(const float4*)&k3W[q * 32 + lc];
            else if (q < 544) preW = *(const float4*)&k3b[(q - 512) * 32 + lc];
            else              preW = *(const float4*)&skW[(q - 544) * 32 + lc];
        }
        // compute on current buffer
        #pragma unroll 16
        for (int kk = 0; kk < KC; kk++) {
            float4 w = *(const float4*)&Ws[buf][kk * 32 + td * 4];
            unsigned long long w01 = pk2(w.x, w.y);
            unsigned long long w23 = pk2(w.z, w.w);
            #pragma unroll
            for (int i = 0; i < 4; i++) {
                float ui = Us[buf][(tp * 4 + i) * US_LD + kk];
                unsigned long long uu = dup2(ui);
                fma2(acc[i * 2],     uu, w01);
                fma2(acc[i * 2 + 1], uu, w23);
            }
        }
        // write next buffer
        if (c < KPB / KC - 1) {
            int nb = buf ^ 1;
            #pragma unroll
            for (int pass = 0; pass < 4; pass++) {
                float* d = &Us[nb][(lr + pass * 32) * US_LD + lc];
                d[0] = preU[pass].x; d[1] = preU[pass].y; d[2] = preU[pass].z; d[3] = preU[pass].w;
            }
            *(float4*)&Ws[nb][lr * 32 + lc] = preW;
            __syncthreads();
        }
    }

    // epilogue: partials to g_Cp[ks][pos][d]
    #pragma unroll
    for (int i = 0; i < 4; i++) {
        int pg = bm * MT + tp * 4 + i;
        float4 o = make_float4(f2lo(acc[i * 2]), f2hi(acc[i * 2]),
                               f2lo(acc[i * 2 + 1]), f2hi(acc[i * 2 + 1]));
        *(float4*)&g_Cp[(ks * NPAD2 + pg) * 32 + td * 4] = o;
    }
}

// ---------------- k_reduce: sum K-split partials + skipb + BN stats ----------------
__global__ void k_reduce(int sel, const float* __restrict__ skb) {
    float* outBuf = sel ? g_bufA : g_bufB;
    __shared__ float st[64];
    int tid = threadIdx.x;
    if (tid < 64) st[tid] = 0.0f;
    __syncthreads();

    int d = tid & 31, pr = tid >> 5;   // pr 0..7
    float sb = skb[d];
    float sA = 0.f, sQ = 0.f;
    #pragma unroll
    for (int i = 0; i < 8; i++) {
        int pos = blockIdx.x * 64 + i * 8 + pr;
        float s = sb;
        #pragma unroll
        for (int ks = 0; ks < KSPLIT; ks++)
            s += g_Cp[(ks * NPAD2 + pos) * 32 + d];
        if (pos < NPOS) {
            outBuf[pos * CCH + d] = s;
            sA += s; sQ += s * s;
        }
    }
    atomicAdd(&st[d], sA);
    atomicAdd(&st[32 + d], sQ);
    __syncthreads();
    if (tid < 64) g_part[blockIdx.x * 64 + tid] = st[tid];
}

// ---------------- BN stats finalize ----------------
__global__ void k_bnstats(const float* __restrict__ gamma, const float* __restrict__ beta) {
    int c = threadIdx.x;
    if (c < 32) {
        float s = 0.f, sq = 0.f;
        for (int b = 0; b < RED_BLKS; b++) {
            s  += g_part[b * 64 + c];
            sq += g_part[b * 64 + 32 + c];
        }
        const float inv = 1.0f / (float)NPOS;
        float mu  = s * inv;
        float var = sq * inv - mu * mu;
        float rs  = rsqrtf(var + 1e-5f);
        float sc  = rs * gamma[c];
        g_bn[c]      = sc;
        g_bn[32 + c] = beta[c] - mu * sc;
    }
}

// ---------------- BN apply + leaky relu ----------------
__global__ void k_bnapply(int sel, float* dst_ext) {
    float* src = sel ? g_bufA : g_bufB;
    float* dst = dst_ext ? dst_ext : src;
    int i = blockIdx.x * blockDim.x + threadIdx.x;
    if (i < NPOS * CCH) {
        int c = i & 31;
        float y = fmaf(src[i], g_bn[c], g_bn[32 + c]);
        dst[i] = fmaxf(y, 0.1f * y);
    }
}

// ---------------- launch ----------------
extern "C" void kernel_launch(void* const* d_in, const int* in_sizes, int n_in,
                              void* d_out, int out_size) {
    const float* et    = (const float*)d_in[0];
    const int*   ty    = (const int*)  d_in[1];
    const float* emb   = (const float*)d_in[2];
    const float* k1W   = (const float*)d_in[3];
    const float* k1b   = (const float*)d_in[4];
    const float* k2W   = (const float*)d_in[5];
    const float* k2b   = (const float*)d_in[6];
    const float* k3W   = (const float*)d_in[7];
    const float* k3b   = (const float*)d_in[8];
    const float* skW   = (const float*)d_in[9];
    const float* skb   = (const float*)d_in[10];
    const float* gamma = (const float*)d_in[11];
    const float* beta  = (const float*)d_in[12];

    k_prep<<<(NPAD2 + 255) / 256, 256>>>(et);
    k_maxtype<<<1, 256>>>(ty);
    k_embed<<<(NPAD2 * CCH + 255) / 256, 256>>>(ty, emb);

    const int dils[4] = {1, 2, 4, 8};
    for (int L = 0; L < 4; L++) {
        int sel = L & 1;
        k_formU<<<NFU, FU_THREADS>>>(sel, dils[L],
            k1W + L * 16, k1b + L * 16, k2W + L * 256, k2b + L * 16);
        k_gemm<<<dim3(NMT, KSPLIT), 256>>>(
            k3W + L * 16384, k3b + L * 1024, skW + L * 1024);
        k_reduce<<<RED_BLKS, 256>>>(sel, skb + L * 32);
        k_bnstats<<<1, 32>>>(gamma + L * 32, beta + L * 32);
        k_bnapply<<<(NPOS * CCH + 255) / 256, 256>>>(
            sel, (L == 3) ? (float*)d_out : nullptr);
    }
}